// round 1
// baseline (speedup 1.0000x reference)
#include <cuda_runtime.h>
#include <math.h>

// Problem constants
constexpr int Bb = 128;       // batch
constexpr int Hh = 1024;      // d_model
constexpr int Ll = 256;       // seq len
constexpr int Nn = 64;        // SSM state size
constexpr int HL = Hh * Ll;   // 262144

// Scratch (allocation-free rule: __device__ globals)
__device__ float g_k[Hh * Ll];            // S4D conv kernel (H, L)   ~1 MB
__device__ float g_y[(size_t)Bb * HL];    // post-GELU activations    ~134 MB

// ---------------------------------------------------------------------------
// helpers
// ---------------------------------------------------------------------------
__device__ __forceinline__ unsigned f2tf(float x) {
    unsigned u;
    asm("cvt.rna.tf32.f32 %0, %1;" : "=r"(u) : "f"(x));
    return u;
}
__device__ __forceinline__ float f2tff(float x) { return __uint_as_float(f2tf(x)); }

__device__ __forceinline__ void mma_tf32(float c[4], const unsigned a[4], const unsigned b[2]) {
    asm volatile(
        "mma.sync.aligned.m16n8k8.row.col.f32.tf32.tf32.f32 "
        "{%0,%1,%2,%3}, {%4,%5,%6,%7}, {%8,%9}, {%0,%1,%2,%3};\n"
        : "+f"(c[0]), "+f"(c[1]), "+f"(c[2]), "+f"(c[3])
        : "r"(a[0]), "r"(a[1]), "r"(a[2]), "r"(a[3]), "r"(b[0]), "r"(b[1]));
}

__device__ __forceinline__ float gelu_tanh(float v) {
    float u = 0.7978845608028654f * (v + 0.044715f * v * v * v);
    return 0.5f * v * (1.0f + tanhf(u));
}

// ---------------------------------------------------------------------------
// Kernel 1: S4D convolution kernel k[h, l]
//   k[h,l] = 2 * Re( sum_n C_disc[h,n] * exp(dtA[h,n])^l )
// Per-block: one h. Threads 0..63 precompute per-n constants (double for
// robustness); then thread l evaluates the n-sum with double-reduced phase.
// ---------------------------------------------------------------------------
__global__ void __launch_bounds__(256) k_kernel(const float* __restrict__ log_dt,
                                                const float* __restrict__ Areal_log,
                                                const float* __restrict__ Aim,
                                                const float* __restrict__ Cre,
                                                const float* __restrict__ Cim) {
    const int h = blockIdx.x;
    const int t = threadIdx.x;

    __shared__ float  s_dare[Nn];   // Re(dt*A)
    __shared__ double s_daim[Nn];   // Im(dt*A) (double: exact phase accumulation)
    __shared__ float  s_cdre[Nn];
    __shared__ float  s_cdim[Nn];

    if (t < Nn) {
        double dt   = exp((double)log_dt[h]);
        double Are  = -exp((double)Areal_log[h * Nn + t]);
        double Aimv = (double)Aim[h * Nn + t];
        double dAre = Are * dt, dAim = Aimv * dt;
        // E = exp(dtA)
        double ex  = exp(dAre);
        double Ere = ex * cos(dAim), Eim = ex * sin(dAim);
        // f = (E - 1) / A
        double den = Are * Are + Aimv * Aimv;
        double nre = Ere - 1.0, nim = Eim;
        double fre = (nre * Are + nim * Aimv) / den;
        double fim = (nim * Are - nre * Aimv) / den;
        double cre = (double)Cre[h * Nn + t], cim = (double)Cim[h * Nn + t];
        s_cdre[t] = (float)(cre * fre - cim * fim);
        s_cdim[t] = (float)(cre * fim + cim * fre);
        s_dare[t] = (float)dAre;
        s_daim[t] = dAim;
    }
    __syncthreads();

    const int l = t;  // 0..255
    const double TWO_PI = 6.283185307179586;
    const double INV_TWO_PI = 0.15915494309189535;
    float acc = 0.0f;
    #pragma unroll 4
    for (int n = 0; n < Nn; n++) {
        float e = __expf(s_dare[n] * (float)l);
        double p = s_daim[n] * (double)l;
        p -= TWO_PI * rint(p * INV_TWO_PI);   // exact range reduction
        float sp, cp;
        sincosf((float)p, &sp, &cp);
        acc += e * (s_cdre[n] * cp - s_cdim[n] * sp);
    }
    g_k[h * Ll + l] = 2.0f * acc;
}

// ---------------------------------------------------------------------------
// Kernel 2: causal conv as per-h Toeplitz GEMM (tf32 mma.sync), fused
// D-skip + tanh-GELU epilogue. Writes g_y (fp32).
//   Block: 128 thr (4 warps), tile M=64(b) x N=64(l), K-chunks of 32 over m.
//   grid: (8 [= 4 l-tiles x 2 b-tiles], 1024 h)
// ---------------------------------------------------------------------------
__global__ void __launch_bounds__(128) conv_kernel(const float* __restrict__ x,
                                                   const float* __restrict__ Dv) {
    const int h  = blockIdx.y;
    const int lt = blockIdx.x >> 1;
    const int bt = blockIdx.x & 1;
    const int l0 = lt * 64, b0 = bt * 64;
    const int t = threadIdx.x;
    const int wid = t >> 5, lane = t & 31;
    const int wm = wid & 1, wn = wid >> 1;     // 2x2 warp grid, warp tile 32x32
    const int g = lane >> 2, r = lane & 3;

    __shared__ float k_sh[Ll];
    __shared__ float Xs[64][36];   // [b][m]  (pad 36 -> conflict-free frag loads)
    __shared__ float Ts[64][36];   // [l][m]  (B col-major view)

    for (int i = t; i < Ll; i += 128) k_sh[i] = f2tff(g_k[h * Ll + i]);

    float acc[2][4][4];
    #pragma unroll
    for (int a = 0; a < 2; a++)
        #pragma unroll
        for (int bnn = 0; bnn < 4; bnn++)
            #pragma unroll
            for (int cq = 0; cq < 4; cq++) acc[a][bnn][cq] = 0.0f;

    const int kend = l0 + 64;      // causal: m <= l
    for (int m0 = 0; m0 < kend; m0 += 32) {
        __syncthreads();
        #pragma unroll
        for (int p = 0; p < 16; p++) {
            int rowi = (t >> 5) + p * 4;   // b-row / l-row
            int ki   = t & 31;             // m within chunk
            Xs[rowi][ki] = f2tff(x[(size_t)(b0 + rowi) * HL + h * Ll + m0 + ki]);
            int d = (l0 + rowi) - (m0 + ki);
            Ts[rowi][ki] = (d >= 0) ? k_sh[d] : 0.0f;
        }
        __syncthreads();
        #pragma unroll
        for (int k8 = 0; k8 < 32; k8 += 8) {
            unsigned afr[2][4], bfr[4][2];
            #pragma unroll
            for (int mi = 0; mi < 2; mi++) {
                int mrow = wm * 32 + mi * 16 + g;
                afr[mi][0] = __float_as_uint(Xs[mrow][k8 + r]);
                afr[mi][1] = __float_as_uint(Xs[mrow + 8][k8 + r]);
                afr[mi][2] = __float_as_uint(Xs[mrow][k8 + r + 4]);
                afr[mi][3] = __float_as_uint(Xs[mrow + 8][k8 + r + 4]);
            }
            #pragma unroll
            for (int ni = 0; ni < 4; ni++) {
                int ncol = wn * 32 + ni * 8 + g;
                bfr[ni][0] = __float_as_uint(Ts[ncol][k8 + r]);
                bfr[ni][1] = __float_as_uint(Ts[ncol][k8 + r + 4]);
            }
            #pragma unroll
            for (int mi = 0; mi < 2; mi++)
                #pragma unroll
                for (int ni = 0; ni < 4; ni++)
                    mma_tf32(acc[mi][ni], afr[mi], bfr[ni]);
        }
    }

    const float Dh = Dv[h];
    #pragma unroll
    for (int mi = 0; mi < 2; mi++) {
        #pragma unroll
        for (int ni = 0; ni < 4; ni++) {
            #pragma unroll
            for (int cq = 0; cq < 4; cq++) {
                int row = b0 + wm * 32 + mi * 16 + g + ((cq >= 2) ? 8 : 0);
                int col = l0 + wn * 32 + ni * 8 + 2 * r + (cq & 1);
                size_t xi = (size_t)row * HL + (size_t)h * Ll + col;
                float v = acc[mi][ni][cq] + Dh * x[xi];
                g_y[xi] = gelu_tanh(v);
            }
        }
    }
}

// ---------------------------------------------------------------------------
// Kernel 3: output projection (tf32 mma.sync) + bias + GLU.
//   Z[g, (b,l)] = sum_h W[g,h] * Y[h,b,l] + bias[g]
//   out[b,g,l] = Z[g] * sigmoid(Z[g+1024]),   g in [0,1024)
// Block: 256 thr (8 warps, 4x2), tile M=128 (64 a-rows g0.. + 64 b-rows
// 1024+g0..), N=128 (l cols within one batch b), K=1024 in chunks of 32.
// Register-prefetch pipeline over K. b-half staged via shared for GLU pairing.
// grid: (16 g-tiles, 2 l-tiles, 128 b) -- g fastest so Y slice reuses in L2.
// ---------------------------------------------------------------------------
__global__ void __launch_bounds__(256) gemm2_kernel(const float* __restrict__ W,
                                                    const float* __restrict__ bias,
                                                    float* __restrict__ out) {
    const int g0 = blockIdx.x * 64;
    const int l0 = blockIdx.y * 128;
    const int b  = blockIdx.z;
    const int t = threadIdx.x;
    const int wid = t >> 5, lane = t & 31;
    const int wm = wid & 3, wn = wid >> 2;   // warp tile 32 x 64
    const int g = lane >> 2, r = lane & 3;

    __shared__ float smem[8832];
    float* Ws = smem;          // [128][36]
    float* Ys = smem + 4608;   // [32][132]

    float acc[2][8][4];
    #pragma unroll
    for (int a = 0; a < 2; a++)
        #pragma unroll
        for (int bnn = 0; bnn < 8; bnn++)
            #pragma unroll
            for (int cq = 0; cq < 4; cq++) acc[a][bnn][cq] = 0.0f;

    const float* ybase = g_y + (size_t)b * HL + l0;

    // prologue: tile h0 = 0 -> smem
    #pragma unroll
    for (int i = 0; i < 4; i++) {
        int f = t + 256 * i;
        int m = f >> 3, kq = f & 7;
        int grow = (m < 64) ? (g0 + m) : (1024 + g0 + m - 64);
        float4 v = *(const float4*)(W + (size_t)grow * 1024 + kq * 4);
        *(float4*)(Ws + m * 36 + kq * 4) =
            make_float4(f2tff(v.x), f2tff(v.y), f2tff(v.z), f2tff(v.w));
        int k = f >> 5, nq = f & 31;
        float4 y = *(const float4*)(ybase + (size_t)k * Ll + nq * 4);
        *(float4*)(Ys + k * 132 + nq * 4) =
            make_float4(f2tff(y.x), f2tff(y.y), f2tff(y.z), f2tff(y.w));
    }

    float4 wreg[4], yreg[4];
    for (int it = 0; it < 32; it++) {
        __syncthreads();
        const int h1 = (it + 1) * 32;
        if (h1 < 1024) {   // prefetch next tile into registers
            #pragma unroll
            for (int i = 0; i < 4; i++) {
                int f = t + 256 * i;
                int m = f >> 3, kq = f & 7;
                int grow = (m < 64) ? (g0 + m) : (1024 + g0 + m - 64);
                wreg[i] = *(const float4*)(W + (size_t)grow * 1024 + h1 + kq * 4);
                int k = f >> 5, nq = f & 31;
                yreg[i] = *(const float4*)(ybase + (size_t)(h1 + k) * Ll + nq * 4);
            }
        }
        // compute current tile
        #pragma unroll
        for (int k8 = 0; k8 < 32; k8 += 8) {
            unsigned afr[2][4], bfr[8][2];
            #pragma unroll
            for (int mi = 0; mi < 2; mi++) {
                int mrow = wm * 32 + mi * 16 + g;
                const float* wp = Ws + mrow * 36 + k8 + r;
                afr[mi][0] = __float_as_uint(wp[0]);
                afr[mi][1] = __float_as_uint(wp[8 * 36]);
                afr[mi][2] = __float_as_uint(wp[4]);
                afr[mi][3] = __float_as_uint(wp[8 * 36 + 4]);
            }
            #pragma unroll
            for (int ni = 0; ni < 8; ni++) {
                int ncol = wn * 64 + ni * 8 + g;
                const float* yp = Ys + (k8 + r) * 132 + ncol;
                bfr[ni][0] = __float_as_uint(yp[0]);
                bfr[ni][1] = __float_as_uint(yp[4 * 132]);
            }
            #pragma unroll
            for (int mi = 0; mi < 2; mi++)
                #pragma unroll
                for (int ni = 0; ni < 8; ni++)
                    mma_tf32(acc[mi][ni], afr[mi], bfr[ni]);
        }
        __syncthreads();
        if (h1 < 1024) {   // drain prefetch regs -> smem
            #pragma unroll
            for (int i = 0; i < 4; i++) {
                int f = t + 256 * i;
                int m = f >> 3, kq = f & 7;
                float4 v = wreg[i];
                *(float4*)(Ws + m * 36 + kq * 4) =
                    make_float4(f2tff(v.x), f2tff(v.y), f2tff(v.z), f2tff(v.w));
                int k = f >> 5, nq = f & 31;
                float4 y = yreg[i];
                *(float4*)(Ys + k * 132 + nq * 4) =
                    make_float4(f2tff(y.x), f2tff(y.y), f2tff(y.z), f2tff(y.w));
            }
        }
    }

    // Epilogue: stage gate half (rows 64..127 -> global 1024+g0+row) w/ bias,
    // then a-half warps apply GLU and write out.
    float* Zb = smem;   // [64][132] reuse
    __syncthreads();
    if (wm >= 2) {
        #pragma unroll
        for (int mi = 0; mi < 2; mi++) {
            #pragma unroll
            for (int ni = 0; ni < 8; ni++) {
                #pragma unroll
                for (int cq = 0; cq < 4; cq++) {
                    int row = (wm - 2) * 32 + mi * 16 + g + ((cq >= 2) ? 8 : 0);
                    int col = wn * 64 + ni * 8 + 2 * r + (cq & 1);
                    Zb[row * 132 + col] = acc[mi][ni][cq] + bias[1024 + g0 + row];
                }
            }
        }
    }
    __syncthreads();
    if (wm < 2) {
        #pragma unroll
        for (int mi = 0; mi < 2; mi++) {
            #pragma unroll
            for (int ni = 0; ni < 8; ni++) {
                #pragma unroll
                for (int cq = 0; cq < 4; cq++) {
                    int row = wm * 32 + mi * 16 + g + ((cq >= 2) ? 8 : 0);
                    int col = wn * 64 + ni * 8 + 2 * r + (cq & 1);
                    float av = acc[mi][ni][cq] + bias[g0 + row];
                    float bv = Zb[row * 132 + col];
                    float sv = 1.0f / (1.0f + __expf(-bv));
                    out[(size_t)b * HL + (size_t)(g0 + row) * Ll + l0 + col] = av * sv;
                }
            }
        }
    }
}

// ---------------------------------------------------------------------------
// launch
// ---------------------------------------------------------------------------
extern "C" void kernel_launch(void* const* d_in, const int* in_sizes, int n_in,
                              void* d_out, int out_size) {
    const float* x         = (const float*)d_in[0];
    const float* log_dt    = (const float*)d_in[1];
    const float* A_real_lg = (const float*)d_in[2];
    const float* A_imag    = (const float*)d_in[3];
    const float* C_re      = (const float*)d_in[4];
    const float* C_im      = (const float*)d_in[5];
    const float* Dv        = (const float*)d_in[6];
    const float* W_out     = (const float*)d_in[7];
    const float* b_out     = (const float*)d_in[8];
    float* out = (float*)d_out;

    k_kernel<<<Hh, 256>>>(log_dt, A_real_lg, A_imag, C_re, C_im);
    conv_kernel<<<dim3(8, Hh, 1), 128>>>(x, Dv);
    gemm2_kernel<<<dim3(16, 2, Bb), 256>>>(W_out, b_out, out);
}

// round 3
// speedup vs baseline: 1.2196x; 1.2196x over previous
#include <cuda_runtime.h>
#include <math.h>

// Problem constants
constexpr int Bb = 128;       // batch
constexpr int Hh = 1024;      // d_model
constexpr int Ll = 256;       // seq len
constexpr int Nn = 64;        // SSM state size
constexpr int HL = Hh * Ll;   // 262144

// Scratch (allocation-free rule: __device__ globals)
__device__ float g_k[Hh * Ll];             // S4D conv kernel (H, L)      ~1 MB
__device__ float g_y[(size_t)Bb * HL];     // post-GELU acts (tf32-rounded) ~134 MB
__device__ float g_w[2048 * 1024];         // tf32-rounded W_out           8 MB

// ---------------------------------------------------------------------------
// helpers
// ---------------------------------------------------------------------------
__device__ __forceinline__ unsigned f2tf(float x) {
    unsigned u;
    asm("cvt.rna.tf32.f32 %0, %1;" : "=r"(u) : "f"(x));
    return u;
}
__device__ __forceinline__ float f2tff(float x) { return __uint_as_float(f2tf(x)); }

__device__ __forceinline__ void mma_tf32(float c[4], const unsigned a[4], const unsigned b[2]) {
    asm volatile(
        "mma.sync.aligned.m16n8k8.row.col.f32.tf32.tf32.f32 "
        "{%0,%1,%2,%3}, {%4,%5,%6,%7}, {%8,%9}, {%0,%1,%2,%3};\n"
        : "+f"(c[0]), "+f"(c[1]), "+f"(c[2]), "+f"(c[3])
        : "r"(a[0]), "r"(a[1]), "r"(a[2]), "r"(a[3]), "r"(b[0]), "r"(b[1]));
}

__device__ __forceinline__ float gelu_tanh(float v) {
    float u = 0.7978845608028654f * (v + 0.044715f * v * v * v);
    return 0.5f * v * (1.0f + tanhf(u));
}

__device__ __forceinline__ void cp_async16(void* smem_dst, const void* gsrc) {
    unsigned s = (unsigned)__cvta_generic_to_shared(smem_dst);
    asm volatile("cp.async.cg.shared.global [%0], [%1], 16;\n" :: "r"(s), "l"(gsrc));
}
__device__ __forceinline__ void cp_commit() { asm volatile("cp.async.commit_group;\n"); }
template <int N> __device__ __forceinline__ void cp_wait() {
    asm volatile("cp.async.wait_group %0;\n" :: "n"(N));
}

// ---------------------------------------------------------------------------
// Kernel 0: round W_out to tf32 once per call
// ---------------------------------------------------------------------------
__global__ void wprep_kernel(const float* __restrict__ W) {
    int i = blockIdx.x * 256 + threadIdx.x;
    g_w[i] = f2tff(W[i]);
}

// ---------------------------------------------------------------------------
// Kernel 1: S4D convolution kernel k[h, l] via binary power tables.
//   E = exp(dtA); E^l = E16^(l>>4) * E^(l&15).  All-FMA hot loop (no MUFU).
// ---------------------------------------------------------------------------
__global__ void __launch_bounds__(256) k_kernel(const float* __restrict__ log_dt,
                                                const float* __restrict__ Areal_log,
                                                const float* __restrict__ Aim,
                                                const float* __restrict__ Cre,
                                                const float* __restrict__ Cim) {
    const int h = blockIdx.x;
    const int t = threadIdx.x;

    __shared__ float2 Tlo[Nn][16];   // E^j,   j=0..15
    __shared__ float2 Thi[Nn][16];   // E^(16j)
    __shared__ float  s_cre[Nn], s_cim[Nn];

    if (t < Nn) {
        float dt   = expf(log_dt[h]);
        float Are  = -expf(Areal_log[h * Nn + t]);
        float Aimv = Aim[h * Nn + t];
        float dAre = Are * dt, dAim = Aimv * dt;
        float s, c;
        float ex = expf(dAre);
        sincosf(dAim, &s, &c);
        float2 E = make_float2(ex * c, ex * s);
        float ex16 = expf(16.0f * dAre);
        sincosf(16.0f * dAim, &s, &c);
        float2 E16 = make_float2(ex16 * c, ex16 * s);
        // C_disc = C * (E - 1) / A
        float den = Are * Are + Aimv * Aimv;
        float nre = E.x - 1.0f, nim = E.y;
        float fre = (nre * Are + nim * Aimv) / den;
        float fim = (nim * Are - nre * Aimv) / den;
        float cre = Cre[h * Nn + t], cim = Cim[h * Nn + t];
        s_cre[t] = cre * fre - cim * fim;
        s_cim[t] = cre * fim + cim * fre;

        float2 p = make_float2(1.0f, 0.0f);
        #pragma unroll
        for (int j = 0; j < 16; j++) {
            Tlo[t][j] = p;
            p = make_float2(p.x * E.x - p.y * E.y, p.x * E.y + p.y * E.x);
        }
        p = make_float2(1.0f, 0.0f);
        #pragma unroll
        for (int j = 0; j < 16; j++) {
            Thi[t][j] = p;
            p = make_float2(p.x * E16.x - p.y * E16.y, p.x * E16.y + p.y * E16.x);
        }
    }
    __syncthreads();

    const int l = t, lo = l & 15, hi = l >> 4;
    float acc = 0.0f;
    #pragma unroll 8
    for (int n = 0; n < Nn; n++) {
        float2 a = Tlo[n][lo], b = Thi[n][hi];
        float re = a.x * b.x - a.y * b.y;
        float im = a.x * b.y + a.y * b.x;
        acc += s_cre[n] * re - s_cim[n] * im;
    }
    g_k[h * Ll + l] = 2.0f * acc;
}

// ---------------------------------------------------------------------------
// Kernel 2: causal conv as per-h Toeplitz GEMM (tf32 mma.sync), fused
// D-skip + tanh-GELU epilogue. Writes g_y TF32-ROUNDED (gemm2 consumes raw).
// ---------------------------------------------------------------------------
__global__ void __launch_bounds__(128) conv_kernel(const float* __restrict__ x,
                                                   const float* __restrict__ Dv) {
    const int h  = blockIdx.y;
    const int lt = blockIdx.x >> 1;
    const int bt = blockIdx.x & 1;
    const int l0 = lt * 64, b0 = bt * 64;
    const int t = threadIdx.x;
    const int lane = t & 31;
    const int wid = t >> 5;
    const int wm = wid & 1, wn = wid >> 1;
    const int g = lane >> 2, r = lane & 3;

    __shared__ float k_sh[Ll];
    __shared__ float Xs[64][36];
    __shared__ float Ts[64][36];

    for (int i = t; i < Ll; i += 128) k_sh[i] = f2tff(g_k[h * Ll + i]);

    float acc[2][4][4];
    #pragma unroll
    for (int a = 0; a < 2; a++)
        #pragma unroll
        for (int bnn = 0; bnn < 4; bnn++)
            #pragma unroll
            for (int cq = 0; cq < 4; cq++) acc[a][bnn][cq] = 0.0f;

    const int kend = l0 + 64;
    for (int m0 = 0; m0 < kend; m0 += 32) {
        __syncthreads();
        #pragma unroll
        for (int p = 0; p < 16; p++) {
            int rowi = (t >> 5) + p * 4;
            int ki   = t & 31;
            Xs[rowi][ki] = f2tff(x[(size_t)(b0 + rowi) * HL + h * Ll + m0 + ki]);
            int d = (l0 + rowi) - (m0 + ki);
            Ts[rowi][ki] = (d >= 0) ? k_sh[d] : 0.0f;
        }
        __syncthreads();
        #pragma unroll
        for (int k8 = 0; k8 < 32; k8 += 8) {
            unsigned afr[2][4], bfr[4][2];
            #pragma unroll
            for (int mi = 0; mi < 2; mi++) {
                int mrow = wm * 32 + mi * 16 + g;
                afr[mi][0] = __float_as_uint(Xs[mrow][k8 + r]);
                afr[mi][1] = __float_as_uint(Xs[mrow + 8][k8 + r]);
                afr[mi][2] = __float_as_uint(Xs[mrow][k8 + r + 4]);
                afr[mi][3] = __float_as_uint(Xs[mrow + 8][k8 + r + 4]);
            }
            #pragma unroll
            for (int ni = 0; ni < 4; ni++) {
                int ncol = wn * 32 + ni * 8 + g;
                bfr[ni][0] = __float_as_uint(Ts[ncol][k8 + r]);
                bfr[ni][1] = __float_as_uint(Ts[ncol][k8 + r + 4]);
            }
            #pragma unroll
            for (int mi = 0; mi < 2; mi++)
                #pragma unroll
                for (int ni = 0; ni < 4; ni++)
                    mma_tf32(acc[mi][ni], afr[mi], bfr[ni]);
        }
    }

    const float Dh = Dv[h];
    #pragma unroll
    for (int mi = 0; mi < 2; mi++) {
        #pragma unroll
        for (int ni = 0; ni < 4; ni++) {
            #pragma unroll
            for (int cq = 0; cq < 4; cq++) {
                int row = b0 + wm * 32 + mi * 16 + g + ((cq >= 2) ? 8 : 0);
                int col = l0 + wn * 32 + ni * 8 + 2 * r + (cq & 1);
                size_t xi = (size_t)row * HL + (size_t)h * Ll + col;
                float v = acc[mi][ni][cq] + Dh * x[xi];
                g_y[xi] = f2tff(gelu_tanh(v));   // pre-round for gemm2
            }
        }
    }
}

// ---------------------------------------------------------------------------
// Kernel 3: output projection + bias + GLU.
//   Tile M=128 (64 a-rows g0.. / 64 gate-rows 1024+g0..), N=256 (all l of b).
//   512 thr = 16 warps (4m x 4n, warp tile 32x64). K=1024 in 16-chunks,
//   4-stage cp.async pipeline. Operands pre-rounded to tf32 (g_w, g_y).
// grid: (16 g-tiles, 128 b) — g fastest so the 1MB Y_b slice reuses in L2.
// ---------------------------------------------------------------------------
constexpr int G2_STAGES = 4;
constexpr int G2_WS_STRIDE = 20;    // floats per W row   (16 used)
constexpr int G2_YS_STRIDE = 264;   // floats per Y row   (256 used)
constexpr int G2_STAGE_FLT = 128 * G2_WS_STRIDE + 16 * G2_YS_STRIDE;  // 6784
constexpr int G2_SMEM_BYTES = G2_STAGES * G2_STAGE_FLT * 4;           // 108544

__global__ void __launch_bounds__(512, 1) gemm2_kernel(const float* __restrict__ bias,
                                                       float* __restrict__ out) {
    extern __shared__ float smem[];
    const int g0 = blockIdx.x * 64;
    const int b  = blockIdx.y;
    const int t = threadIdx.x;
    const int lane = t & 31;
    const int wid = t >> 5;
    const int wm = wid & 3, wn = wid >> 2;     // 4x4 warps, tile 32x64
    const int g = lane >> 2, r = lane & 3;

    const float* ybase = g_y + (size_t)b * HL;

    // per-thread copy assignments (fixed):
    //  W: 512 x 16B chunks -> thread t: row m=t>>2, chunk q=t&3
    const int wm_row = t >> 2, wq = t & 3;
    const int wgrow = (wm_row < 64) ? (g0 + wm_row) : (960 + g0 + wm_row);
    const float* wsrc = g_w + (size_t)wgrow * 1024 + wq * 4;
    //  Y: 1024 x 16B chunks -> thread t handles idx {t, t+512}
    const int yk0 = t >> 6, yq0 = t & 63;

    auto issue = [&](int chunk) {
        float* st = smem + (chunk & (G2_STAGES - 1)) * G2_STAGE_FLT;
        float* Ws = st;
        float* Ys = st + 128 * G2_WS_STRIDE;
        const int h0 = chunk * 16;
        cp_async16(Ws + wm_row * G2_WS_STRIDE + wq * 4, wsrc + h0);
        cp_async16(Ys + yk0 * G2_YS_STRIDE + yq0 * 4,
                   ybase + (size_t)(h0 + yk0) * Ll + yq0 * 4);
        cp_async16(Ys + (yk0 + 8) * G2_YS_STRIDE + yq0 * 4,
                   ybase + (size_t)(h0 + yk0 + 8) * Ll + yq0 * 4);
        cp_commit();
    };

    float acc[2][8][4];
    #pragma unroll
    for (int a = 0; a < 2; a++)
        #pragma unroll
        for (int bnn = 0; bnn < 8; bnn++)
            #pragma unroll
            for (int cq = 0; cq < 4; cq++) acc[a][bnn][cq] = 0.0f;

    #pragma unroll
    for (int s = 0; s < G2_STAGES - 1; s++) issue(s);

    const int NCHUNK = 64;
    for (int it = 0; it < NCHUNK; it++) {
        cp_wait<G2_STAGES - 2>();
        __syncthreads();
        const float* st = smem + (it & (G2_STAGES - 1)) * G2_STAGE_FLT;
        const float* Ws = st;
        const float* Ys = st + 128 * G2_WS_STRIDE;
        #pragma unroll
        for (int k8 = 0; k8 < 16; k8 += 8) {
            unsigned afr[2][4], bfr[8][2];
            #pragma unroll
            for (int mi = 0; mi < 2; mi++) {
                const float* wp = Ws + (wm * 32 + mi * 16 + g) * G2_WS_STRIDE + k8 + r;
                afr[mi][0] = __float_as_uint(wp[0]);
                afr[mi][1] = __float_as_uint(wp[8 * G2_WS_STRIDE]);
                afr[mi][2] = __float_as_uint(wp[4]);
                afr[mi][3] = __float_as_uint(wp[8 * G2_WS_STRIDE + 4]);
            }
            #pragma unroll
            for (int ni = 0; ni < 8; ni++) {
                const float* yp = Ys + (k8 + r) * G2_YS_STRIDE + wn * 64 + ni * 8 + g;
                bfr[ni][0] = __float_as_uint(yp[0]);
                bfr[ni][1] = __float_as_uint(yp[4 * G2_YS_STRIDE]);
            }
            #pragma unroll
            for (int mi = 0; mi < 2; mi++)
                #pragma unroll
                for (int ni = 0; ni < 8; ni++)
                    mma_tf32(acc[mi][ni], afr[mi], bfr[ni]);
        }
        __syncthreads();
        if (it + G2_STAGES - 1 < NCHUNK) issue(it + G2_STAGES - 1);
    }

    // Epilogue: gate half (rows 64..127) -> smem with bias, then GLU.
    float* Zb = smem;   // [64][264] = 67.6 KB, fits in 108.5 KB
    __syncthreads();
    if (wm >= 2) {
        #pragma unroll
        for (int mi = 0; mi < 2; mi++)
            #pragma unroll
            for (int ni = 0; ni < 8; ni++)
                #pragma unroll
                for (int cq = 0; cq < 4; cq++) {
                    int row = (wm - 2) * 32 + mi * 16 + g + ((cq >= 2) ? 8 : 0);
                    int col = wn * 64 + ni * 8 + 2 * r + (cq & 1);
                    Zb[row * G2_YS_STRIDE + col] = acc[mi][ni][cq] + bias[1024 + g0 + row];
                }
    }
    __syncthreads();
    if (wm < 2) {
        #pragma unroll
        for (int mi = 0; mi < 2; mi++)
            #pragma unroll
            for (int ni = 0; ni < 8; ni++)
                #pragma unroll
                for (int cq = 0; cq < 4; cq++) {
                    int row = wm * 32 + mi * 16 + g + ((cq >= 2) ? 8 : 0);
                    int col = wn * 64 + ni * 8 + 2 * r + (cq & 1);
                    float av = acc[mi][ni][cq] + bias[g0 + row];
                    float bv = Zb[row * G2_YS_STRIDE + col];
                    float sv = 1.0f / (1.0f + __expf(-bv));
                    out[(size_t)b * HL + (size_t)(g0 + row) * Ll + col] = av * sv;
                }
    }
}

// ---------------------------------------------------------------------------
// launch
// ---------------------------------------------------------------------------
extern "C" void kernel_launch(void* const* d_in, const int* in_sizes, int n_in,
                              void* d_out, int out_size) {
    const float* x         = (const float*)d_in[0];
    const float* log_dt    = (const float*)d_in[1];
    const float* A_real_lg = (const float*)d_in[2];
    const float* A_imag    = (const float*)d_in[3];
    const float* C_re      = (const float*)d_in[4];
    const float* C_im      = (const float*)d_in[5];
    const float* Dv        = (const float*)d_in[6];
    const float* W_out     = (const float*)d_in[7];
    const float* b_out     = (const float*)d_in[8];
    float* out = (float*)d_out;

    cudaFuncSetAttribute(gemm2_kernel, cudaFuncAttributeMaxDynamicSharedMemorySize,
                         G2_SMEM_BYTES);

    wprep_kernel<<<2048 * 1024 / 256, 256>>>(W_out);
    k_kernel<<<Hh, 256>>>(log_dt, A_real_lg, A_imag, C_re, C_im);
    conv_kernel<<<dim3(8, Hh, 1), 128>>>(x, Dv);
    gemm2_kernel<<<dim3(16, Bb), 512, G2_SMEM_BYTES>>>(b_out, out);
}